// round 6
// baseline (speedup 1.0000x reference)
#include <cuda_runtime.h>
#include <math.h>
#include <stdint.h>

#define BB 32
#define GG 64
#define NN 4096
#define CC 384
#define NSEG 16
#define SCALE 0.051031036307982884f  /* 384^-0.5 */

// ---------------- scratch (device globals; no allocation allowed) ----------------
__device__ float g_Wq[CC*CC];        // q_w.T @ k_w
__device__ float g_Mm[CC*CC];        // p_w @ v_w
__device__ float g_bq2[CC];          // q_b @ k_w
__device__ float g_u[CC];            // q_w.T @ k_b
__device__ float g_pvb[CC];          // p_w @ v_b
__device__ float g_s0[1];            // q_b . k_b
__device__ float g_b2p[12*CC];       // partials for bq2
__device__ float g_up[12*CC];        // partials for u
__device__ float g_q2[BB*GG*CC];     // query @ Wq + bq2
__device__ float g_t[BB*GG];         // per (b,g) bias
__device__ int   g_idx[BB*NN];       // argmax group per (b,n)
__device__ int   g_cnt[BB*GG];       // counts per (b,g)
__device__ float g_Sp[(size_t)NSEG*BB*GG*CC]; // n-segment partial key sums

// ---------------- f32x2 packed helpers (sm_103a) ----------------
__device__ __forceinline__ void fma_f32x2(unsigned long long& d, unsigned long long a,
                                          unsigned long long b, unsigned long long c) {
    asm("fma.rn.f32x2 %0, %1, %2, %3;" : "=l"(d) : "l"(a), "l"(b), "l"(c));
}
__device__ __forceinline__ void unpack2(float& lo, float& hi, unsigned long long v) {
    asm("mov.b64 {%0, %1}, %2;" : "=f"(lo), "=f"(hi) : "l"(v));
}

// ---------------- zero counts ----------------
__global__ void k_zero(int* cnt) {
    int t = blockIdx.x * blockDim.x + threadIdx.x;
    if (t < BB*GG) cnt[t] = 0;
}

// ---------------- parallel precompute: column reductions (partials) ----------------
__global__ void __launch_bounds__(CC) k_prep_cols(const float* __restrict__ qw,
                                                  const float* __restrict__ qb,
                                                  const float* __restrict__ kw,
                                                  const float* __restrict__ kb) {
    int j = threadIdx.x;
    int c0 = blockIdx.x * 32;
    float b2 = 0.f, u = 0.f;
    #pragma unroll 8
    for (int c = c0; c < c0 + 32; c++) {
        b2 += qb[c] * kw[(size_t)c * CC + j];
        u  += qw[(size_t)c * CC + j] * kb[c];
    }
    g_b2p[blockIdx.x * CC + j] = b2;
    g_up [blockIdx.x * CC + j] = u;
}

__global__ void k_prep_red() {
    int j = threadIdx.x;
    float b2 = 0.f, u = 0.f;
    #pragma unroll
    for (int p = 0; p < 12; p++) { b2 += g_b2p[p * CC + j]; u += g_up[p * CC + j]; }
    g_bq2[j] = b2; g_u[j] = u;
}

__global__ void __launch_bounds__(128) k_prep_pv(const float* __restrict__ pw,
                                                 const float* __restrict__ vb,
                                                 const float* __restrict__ qb,
                                                 const float* __restrict__ kb) {
    int w = threadIdx.x >> 5, lane = threadIdx.x & 31;
    if (blockIdx.x == 96) {
        if (w == 0) {
            float s = 0.f;
            for (int c = lane; c < CC; c += 32) s += qb[c] * kb[c];
            #pragma unroll
            for (int o = 16; o; o >>= 1) s += __shfl_xor_sync(0xFFFFFFFFu, s, o);
            if (lane == 0) g_s0[0] = s;
        }
        return;
    }
    int j = blockIdx.x * 4 + w;
    float s = 0.f;
    for (int c = lane; c < CC; c += 32) s += pw[(size_t)j * CC + c] * vb[c];
    #pragma unroll
    for (int o = 16; o; o >>= 1) s += __shfl_xor_sync(0xFFFFFFFFu, s, o);
    if (lane == 0) g_pvb[j] = s;
}

// ---------------- generic 64x64-tile fp32 GEMM ----------------
// AM: 0 = A row-major; 1 = A k-major; 2 = row-major sum of NSEG partials
// BM: 0 = B k-major;   1 = B n-major
// EPI:0 = store; 1 = +bias[j]; 2 = out epilogue
template<int AM, int BM, int EPI>
__global__ void __launch_bounds__(256) k_gemm64(const float* __restrict__ A,
                                                const float* __restrict__ Bm,
                                                float* __restrict__ Cc,
                                                const float* __restrict__ bias,
                                                const int* __restrict__ cnt,
                                                const float* __restrict__ pvb) {
    __shared__ float As[16][68];
    __shared__ float Bs[16][68];
    int j0 = blockIdx.x * 64, i0 = blockIdx.y * 64;
    int tid = threadIdx.x;
    float acc[4][4] = {};
    for (int k0 = 0; k0 < CC; k0 += 16) {
        if (AM == 1) {
            int kk = tid >> 4, i4 = (tid & 15) * 4;
            *(float4*)&As[kk][i4] = *(const float4*)&A[(size_t)(k0 + kk) * CC + i0 + i4];
        } else {
            int r = tid >> 2, kq = (tid & 3) * 4;
            float4 v;
            if (AM == 2) {
                const float* p = &A[(size_t)(i0 + r) * CC + k0 + kq];
                const size_t PS = (size_t)BB * GG * CC;
                float4 s = *(const float4*)p;
                #pragma unroll
                for (int q = 1; q < NSEG; q++) {
                    float4 vq = *(const float4*)(p + (size_t)q * PS);
                    s.x += vq.x; s.y += vq.y; s.z += vq.z; s.w += vq.w;
                }
                v = s;
            } else {
                v = *(const float4*)&A[(size_t)(i0 + r) * CC + k0 + kq];
            }
            As[kq + 0][r] = v.x; As[kq + 1][r] = v.y;
            As[kq + 2][r] = v.z; As[kq + 3][r] = v.w;
        }
        if (BM == 0) {
            int kk = tid >> 4, j4 = (tid & 15) * 4;
            *(float4*)&Bs[kk][j4] = *(const float4*)&Bm[(size_t)(k0 + kk) * CC + j0 + j4];
        } else {
            int jr = tid >> 2, kq = (tid & 3) * 4;
            float4 v = *(const float4*)&Bm[(size_t)(j0 + jr) * CC + k0 + kq];
            Bs[kq + 0][jr] = v.x; Bs[kq + 1][jr] = v.y;
            Bs[kq + 2][jr] = v.z; Bs[kq + 3][jr] = v.w;
        }
        __syncthreads();
        int ty = tid >> 4, tx = tid & 15;
        #pragma unroll
        for (int kk = 0; kk < 16; kk++) {
            float4 a4 = *(const float4*)&As[kk][ty * 4];
            float4 b4 = *(const float4*)&Bs[kk][tx * 4];
            float av[4] = {a4.x, a4.y, a4.z, a4.w};
            float bv[4] = {b4.x, b4.y, b4.z, b4.w};
            #pragma unroll
            for (int i = 0; i < 4; i++)
                #pragma unroll
                for (int j = 0; j < 4; j++)
                    acc[i][j] += av[i] * bv[j];
        }
        __syncthreads();
    }
    int ty = tid >> 4, tx = tid & 15;
    #pragma unroll
    for (int i = 0; i < 4; i++) {
        int r = i0 + ty * 4 + i;
        #pragma unroll
        for (int j = 0; j < 4; j++) {
            int c = j0 + tx * 4 + j;
            float v = acc[i][j];
            if (EPI == 1) v += bias[c];
            if (EPI == 2) {
                float cf = (float)cnt[r];
                v = (v + cf * pvb[c]) / (cf + 1.0f) + bias[c];
            }
            Cc[(size_t)r * CC + c] = v;
        }
    }
}

// ---------------- t[r] = query[r,:].u + s0 ----------------
__global__ void k_t(const float* __restrict__ query) {
    int r = blockIdx.x * 8 + threadIdx.y;
    int lane = threadIdx.x;
    float s = 0.f;
    for (int c = lane; c < CC; c += 32) s += query[(size_t)r * CC + c] * g_u[c];
    #pragma unroll
    for (int o = 16; o; o >>= 1) s += __shfl_xor_sync(0xFFFFFFFFu, s, o);
    if (lane == 0) g_t[r] = s + g_s0[0];
}

// ===== fused logits + softmax(over G) + argmax + counts =====
// Block: one b, 128-n tile, all 64 g. 128 threads; 8g x 8n micro-tile; f32x2 FMA.
// A (q2) stored DUPLICATED in smem -> LDS.128 yields (a,a) register pairs, no packing MOVs.
__global__ void __launch_bounds__(128) k_attn(const float* __restrict__ key,
                                              float* __restrict__ soft,
                                              int* __restrict__ idxp,
                                              int* __restrict__ cntp) {
    __shared__ __align__(16) float sAd[16][136];  // duplicated A: [kk][2g],[2g+1]
    __shared__ __align__(16) float sB[16][136];
    __shared__ float rV[8][128];
    __shared__ int   rI[8][128];
    __shared__ float rM[128];
    __shared__ int   rA[128];
    __shared__ float rS[128];
    __shared__ float tsm[GG];

    int b = blockIdx.y;
    int n_base = blockIdx.x * 128;
    int tid = threadIdx.x;
    if (tid < GG) tsm[tid] = g_t[b * GG + tid];

    const float* q2 = g_q2 + (size_t)b * GG * CC;
    const float* kp = key + ((size_t)b * NN + n_base) * CC;

    unsigned long long acc2[8][4];
    #pragma unroll
    for (int i = 0; i < 8; i++)
        #pragma unroll
        for (int j = 0; j < 4; j++) acc2[i][j] = 0ULL;

    for (int k0 = 0; k0 < CC; k0 += 16) {
        {   // A: 64g x 16k, duplicated (8 src floats -> 8 STS.64)
            int g = tid >> 1, ks = (tid & 1) * 8;
            float4 v0 = *(const float4*)&q2[(size_t)g * CC + k0 + ks];
            float4 v1 = *(const float4*)&q2[(size_t)g * CC + k0 + ks + 4];
            float f[8] = {v0.x, v0.y, v0.z, v0.w, v1.x, v1.y, v1.z, v1.w};
            #pragma unroll
            for (int i = 0; i < 8; i++)
                *(float2*)&sAd[ks + i][2 * g] = make_float2(f[i], f[i]);
        }
        #pragma unroll
        for (int p = 0; p < 4; p++) {  // B: 128n x 16k
            int nn = (tid >> 2) + p * 32, kq = (tid & 3) * 4;
            float4 v = *(const float4*)&kp[(size_t)nn * CC + k0 + kq];
            sB[kq + 0][nn] = v.x; sB[kq + 1][nn] = v.y;
            sB[kq + 2][nn] = v.z; sB[kq + 3][nn] = v.w;
        }
        __syncthreads();
        int ty = tid >> 4, tx = tid & 15;
        #pragma unroll
        for (int kk = 0; kk < 16; kk++) {
            ulonglong2 a01 = *(const ulonglong2*)&sAd[kk][ty * 16 + 0];
            ulonglong2 a23 = *(const ulonglong2*)&sAd[kk][ty * 16 + 4];
            ulonglong2 a45 = *(const ulonglong2*)&sAd[kk][ty * 16 + 8];
            ulonglong2 a67 = *(const ulonglong2*)&sAd[kk][ty * 16 + 12];
            ulonglong2 b01 = *(const ulonglong2*)&sB[kk][tx * 8 + 0];
            ulonglong2 b23 = *(const ulonglong2*)&sB[kk][tx * 8 + 4];
            unsigned long long av[8] = {a01.x, a01.y, a23.x, a23.y,
                                        a45.x, a45.y, a67.x, a67.y};
            unsigned long long bv[4] = {b01.x, b01.y, b23.x, b23.y};
            #pragma unroll
            for (int i = 0; i < 8; i++)
                #pragma unroll
                for (int j = 0; j < 4; j++)
                    fma_f32x2(acc2[i][j], av[i], bv[j], acc2[i][j]);
        }
        __syncthreads();
    }

    int ty = tid >> 4, tx = tid & 15;
    // unpack + scale + bias
    float e[8][8];
    #pragma unroll
    for (int i = 0; i < 8; i++) {
        float tb = tsm[ty * 8 + i];
        #pragma unroll
        for (int j = 0; j < 4; j++) {
            float lo, hi;
            unpack2(lo, hi, acc2[i][j]);
            e[i][2 * j]     = SCALE * (lo + tb);
            e[i][2 * j + 1] = SCALE * (hi + tb);
        }
    }
    // phase 1: local max per col (first-max wins)
    #pragma unroll
    for (int j = 0; j < 8; j++) {
        float m = e[0][j]; int am = 0;
        #pragma unroll
        for (int i = 1; i < 8; i++)
            if (e[i][j] > m) { m = e[i][j]; am = i; }
        rV[ty][tx * 8 + j] = m;
        rI[ty][tx * 8 + j] = ty * 8 + am;
    }
    __syncthreads();
    {   // reduce max across ty (ascending -> first max wins)
        float m = rV[0][tid]; int am = rI[0][tid];
        #pragma unroll
        for (int t = 1; t < 8; t++) {
            float v = rV[t][tid];
            if (v > m) { m = v; am = rI[t][tid]; }
        }
        rM[tid] = m; rA[tid] = am;
    }
    __syncthreads();
    // phase 2: exp + partial sums
    #pragma unroll
    for (int j = 0; j < 8; j++) {
        float mj = rM[tx * 8 + j];
        float s = 0.f;
        #pragma unroll
        for (int i = 0; i < 8; i++) { e[i][j] = __expf(e[i][j] - mj); s += e[i][j]; }
        rV[ty][tx * 8 + j] = s;   // reuse rV for sums
    }
    __syncthreads();
    {   // total sums + argmax outputs
        float s = 0.f;
        #pragma unroll
        for (int t = 0; t < 8; t++) s += rV[t][tid];
        rS[tid] = 1.0f / s;
        int am = rA[tid];
        idxp[b * NN + n_base + tid] = am;
        atomicAdd(&cntp[b * GG + am], 1);
    }
    __syncthreads();
    // phase 3: normalize + write soft
    float* outp = soft + (size_t)b * GG * NN + n_base + tx * 8;
    float inv[8];
    #pragma unroll
    for (int j = 0; j < 8; j++) inv[j] = rS[tx * 8 + j];
    #pragma unroll
    for (int i = 0; i < 8; i++) {
        int g = ty * 8 + i;
        float o[8];
        #pragma unroll
        for (int j = 0; j < 8; j++) o[j] = e[i][j] * inv[j];
        *(float4*)&outp[(size_t)g * NN + 0] = *(float4*)&o[0];
        *(float4*)&outp[(size_t)g * NN + 4] = *(float4*)&o[4];
    }
}

// ---------------- segment sums of key rows by argmax group ----------------
__global__ void __launch_bounds__(128) k_seg(const float* __restrict__ key) {
    __shared__ float S[GG][128];
    __shared__ int sidx[256];
    int ns = blockIdx.x, cb = blockIdx.y, b = blockIdx.z;
    int tid = threadIdx.x;
    int c0 = cb * 128, nb = ns * 256;
    for (int i = tid; i < GG * 128; i += 128) ((float*)S)[i] = 0.f;
    for (int i = tid; i < 256; i += 128) sidx[i] = g_idx[b * NN + nb + i];
    __syncthreads();
    const float* kp = key + ((size_t)(b * NN + nb)) * CC + c0;
    for (int n = 0; n < 256; n += 8) {
        float x[8];
        #pragma unroll
        for (int i = 0; i < 8; i++) x[i] = kp[(size_t)(n + i) * CC + tid];
        #pragma unroll
        for (int i = 0; i < 8; i++) S[sidx[n + i]][tid] += x[i];
    }
    __syncthreads();
    float* dst = g_Sp + (size_t)ns * BB * GG * CC + (size_t)b * GG * CC + c0 + tid;
    for (int g = 0; g < GG; g++) dst[(size_t)g * CC] = S[g][tid];
}

// ---------------- launcher ----------------
extern "C" void kernel_launch(void* const* d_in, const int* in_sizes, int n_in,
                              void* d_out, int out_size) {
    const float* query = (const float*)d_in[0];
    const float* key   = (const float*)d_in[1];
    const float* q_w   = (const float*)d_in[2];
    const float* q_b   = (const float*)d_in[3];
    const float* k_w   = (const float*)d_in[4];
    const float* k_b   = (const float*)d_in[5];
    const float* v_w   = (const float*)d_in[6];
    const float* v_b   = (const float*)d_in[7];
    const float* p_w   = (const float*)d_in[8];
    const float* p_b   = (const float*)d_in[9];
    (void)n_in; (void)in_sizes;

    float* out  = (float*)d_out;
    float* soft = out + ((size_t)out_size - (size_t)BB * GG * NN);

    float *pWq, *pMm, *pbq2, *pq2, *ppvb, *pSp;
    int *pidx, *pcnt;
    cudaGetSymbolAddress((void**)&pWq,  g_Wq);
    cudaGetSymbolAddress((void**)&pMm,  g_Mm);
    cudaGetSymbolAddress((void**)&pbq2, g_bq2);
    cudaGetSymbolAddress((void**)&pq2,  g_q2);
    cudaGetSymbolAddress((void**)&ppvb, g_pvb);
    cudaGetSymbolAddress((void**)&pSp,  g_Sp);
    cudaGetSymbolAddress((void**)&pidx, g_idx);
    cudaGetSymbolAddress((void**)&pcnt, g_cnt);

    // 1. zero counts
    k_zero<<<2, 1024>>>(pcnt);
    // 2. parallel precomputes
    k_prep_cols<<<12, CC>>>(q_w, q_b, k_w, k_b);
    k_prep_pv<<<97, 128>>>(p_w, v_b, q_b, k_b);
    k_prep_red<<<1, CC>>>();
    // 3. Wq = q_w.T @ k_w ; Mm = p_w @ v_w
    k_gemm64<1, 0, 0><<<dim3(6, 6), 256>>>(q_w, k_w, pWq, nullptr, nullptr, nullptr);
    k_gemm64<0, 0, 0><<<dim3(6, 6), 256>>>(p_w, v_w, pMm, nullptr, nullptr, nullptr);
    // 4. t[r]
    k_t<<<BB * GG / 8, dim3(32, 8)>>>(query);
    // 5. q2 = query @ Wq + bq2
    k_gemm64<0, 0, 1><<<dim3(6, 32), 256>>>(query, pWq, pq2, pbq2, nullptr, nullptr);
    // 6. fused logits + softmax + argmax + counts
    k_attn<<<dim3(NN / 128, BB), 128>>>(key, soft, pidx, pcnt);
    // 7. segment sums of key
    k_seg<<<dim3(NSEG, 3, BB), 128>>>(key);
    // 8. out = (S @ Mm.T + cnt*pvb)/(cnt+1) + p_b
    k_gemm64<2, 1, 2><<<dim3(6, 32), 256>>>(pSp, pMm, out, p_b, pcnt, ppvb);
}

// round 7
// speedup vs baseline: 1.1667x; 1.1667x over previous
#include <cuda_runtime.h>
#include <math.h>
#include <stdint.h>

#define BB 32
#define GG 64
#define NN 4096
#define CC 384
#define NSEG 8
#define SCALE 0.051031036307982884f  /* 384^-0.5 */

// ---------------- scratch (device globals; no allocation allowed) ----------------
__device__ float g_Wq[CC*CC];        // q_w.T @ k_w
__device__ float g_Mm[CC*CC];        // p_w @ v_w
__device__ float g_bq2[CC];          // q_b @ k_w
__device__ float g_u[CC];            // q_w.T @ k_b
__device__ float g_pvb[CC];          // p_w @ v_b
__device__ float g_s0[1];            // q_b . k_b
__device__ float g_b2p[12*CC];       // partials for bq2
__device__ float g_up[12*CC];        // partials for u
__device__ float g_q2[BB*GG*CC];     // query @ Wq + bq2
__device__ float g_t[BB*GG];         // per (b,g) bias
__device__ int   g_idx[BB*NN];       // argmax group per (b,n)
__device__ int   g_cnt[BB*GG];       // counts per (b,g)
__device__ float g_Sp[(size_t)NSEG*BB*GG*CC]; // n-segment partial key sums

// ---------------- f32x2 packed helpers (sm_103a) ----------------
__device__ __forceinline__ void fma_f32x2(unsigned long long& d, unsigned long long a,
                                          unsigned long long b, unsigned long long c) {
    asm("fma.rn.f32x2 %0, %1, %2, %3;" : "=l"(d) : "l"(a), "l"(b), "l"(c));
}
__device__ __forceinline__ unsigned long long pack2(float lo, float hi) {
    unsigned long long d;
    asm("mov.b64 %0, {%1, %2};" : "=l"(d) : "f"(lo), "f"(hi));
    return d;
}
__device__ __forceinline__ void unpack2(float& lo, float& hi, unsigned long long v) {
    asm("mov.b64 {%0, %1}, %2;" : "=f"(lo), "=f"(hi) : "l"(v));
}

// ---------------- zero counts ----------------
__global__ void k_zero(int* cnt) {
    int t = blockIdx.x * blockDim.x + threadIdx.x;
    if (t < BB*GG) cnt[t] = 0;
}

// ---------------- parallel precompute: column reductions (partials) ----------------
__global__ void __launch_bounds__(CC) k_prep_cols(const float* __restrict__ qw,
                                                  const float* __restrict__ qb,
                                                  const float* __restrict__ kw,
                                                  const float* __restrict__ kb) {
    int j = threadIdx.x;
    int c0 = blockIdx.x * 32;
    float b2 = 0.f, u = 0.f;
    #pragma unroll 8
    for (int c = c0; c < c0 + 32; c++) {
        b2 += qb[c] * kw[(size_t)c * CC + j];
        u  += qw[(size_t)c * CC + j] * kb[c];
    }
    g_b2p[blockIdx.x * CC + j] = b2;
    g_up [blockIdx.x * CC + j] = u;
}

__global__ void k_prep_red() {
    int j = threadIdx.x;
    float b2 = 0.f, u = 0.f;
    #pragma unroll
    for (int p = 0; p < 12; p++) { b2 += g_b2p[p * CC + j]; u += g_up[p * CC + j]; }
    g_bq2[j] = b2; g_u[j] = u;
}

__global__ void __launch_bounds__(128) k_prep_pv(const float* __restrict__ pw,
                                                 const float* __restrict__ vb,
                                                 const float* __restrict__ qb,
                                                 const float* __restrict__ kb) {
    int w = threadIdx.x >> 5, lane = threadIdx.x & 31;
    if (blockIdx.x == 96) {
        if (w == 0) {
            float s = 0.f;
            for (int c = lane; c < CC; c += 32) s += qb[c] * kb[c];
            #pragma unroll
            for (int o = 16; o; o >>= 1) s += __shfl_xor_sync(0xFFFFFFFFu, s, o);
            if (lane == 0) g_s0[0] = s;
        }
        return;
    }
    int j = blockIdx.x * 4 + w;
    float s = 0.f;
    for (int c = lane; c < CC; c += 32) s += pw[(size_t)j * CC + c] * vb[c];
    #pragma unroll
    for (int o = 16; o; o >>= 1) s += __shfl_xor_sync(0xFFFFFFFFu, s, o);
    if (lane == 0) g_pvb[j] = s;
}

// ---------------- generic 64x64-tile fp32 GEMM (f32x2 inner) ----------------
// AM: 0 = A row-major; 1 = A k-major; 2 = row-major sum of NSEG partials
// BM: 0 = B k-major;   1 = B n-major
// EPI:0 = store; 1 = +bias[j]; 2 = out epilogue
template<int AM, int BM, int EPI>
__global__ void __launch_bounds__(256) k_gemm64(const float* __restrict__ A,
                                                const float* __restrict__ Bm,
                                                float* __restrict__ Cc,
                                                const float* __restrict__ bias,
                                                const int* __restrict__ cnt,
                                                const float* __restrict__ pvb) {
    __shared__ __align__(16) float As[16][68];
    __shared__ __align__(16) float Bs[16][68];
    int j0 = blockIdx.x * 64, i0 = blockIdx.y * 64;
    int tid = threadIdx.x;
    unsigned long long acc2[4][2];
    #pragma unroll
    for (int i = 0; i < 4; i++) { acc2[i][0] = 0ULL; acc2[i][1] = 0ULL; }
    for (int k0 = 0; k0 < CC; k0 += 16) {
        if (AM == 1) {
            int kk = tid >> 4, i4 = (tid & 15) * 4;
            *(float4*)&As[kk][i4] = *(const float4*)&A[(size_t)(k0 + kk) * CC + i0 + i4];
        } else {
            int r = tid >> 2, kq = (tid & 3) * 4;
            float4 v;
            if (AM == 2) {
                const float* p = &A[(size_t)(i0 + r) * CC + k0 + kq];
                const size_t PS = (size_t)BB * GG * CC;
                float4 s = *(const float4*)p;
                #pragma unroll
                for (int q = 1; q < NSEG; q++) {
                    float4 vq = *(const float4*)(p + (size_t)q * PS);
                    s.x += vq.x; s.y += vq.y; s.z += vq.z; s.w += vq.w;
                }
                v = s;
            } else {
                v = *(const float4*)&A[(size_t)(i0 + r) * CC + k0 + kq];
            }
            As[kq + 0][r] = v.x; As[kq + 1][r] = v.y;
            As[kq + 2][r] = v.z; As[kq + 3][r] = v.w;
        }
        if (BM == 0) {
            int kk = tid >> 4, j4 = (tid & 15) * 4;
            *(float4*)&Bs[kk][j4] = *(const float4*)&Bm[(size_t)(k0 + kk) * CC + j0 + j4];
        } else {
            int jr = tid >> 2, kq = (tid & 3) * 4;
            float4 v = *(const float4*)&Bm[(size_t)(j0 + jr) * CC + k0 + kq];
            Bs[kq + 0][jr] = v.x; Bs[kq + 1][jr] = v.y;
            Bs[kq + 2][jr] = v.z; Bs[kq + 3][jr] = v.w;
        }
        __syncthreads();
        int ty = tid >> 4, tx = tid & 15;
        #pragma unroll
        for (int kk = 0; kk < 16; kk++) {
            float4 a4 = *(const float4*)&As[kk][ty * 4];
            ulonglong2 bb = *(const ulonglong2*)&Bs[kk][tx * 4];
            unsigned long long av[4] = {pack2(a4.x, a4.x), pack2(a4.y, a4.y),
                                        pack2(a4.z, a4.z), pack2(a4.w, a4.w)};
            #pragma unroll
            for (int i = 0; i < 4; i++) {
                fma_f32x2(acc2[i][0], av[i], bb.x, acc2[i][0]);
                fma_f32x2(acc2[i][1], av[i], bb.y, acc2[i][1]);
            }
        }
        __syncthreads();
    }
    int ty = tid >> 4, tx = tid & 15;
    #pragma unroll
    for (int i = 0; i < 4; i++) {
        int r = i0 + ty * 4 + i;
        float a0, a1, a2, a3;
        unpack2(a0, a1, acc2[i][0]);
        unpack2(a2, a3, acc2[i][1]);
        float accv[4] = {a0, a1, a2, a3};
        #pragma unroll
        for (int j = 0; j < 4; j++) {
            int c = j0 + tx * 4 + j;
            float v = accv[j];
            if (EPI == 1) v += bias[c];
            if (EPI == 2) {
                float cf = (float)cnt[r];
                v = (v + cf * pvb[c]) / (cf + 1.0f) + bias[c];
            }
            Cc[(size_t)r * CC + c] = v;
        }
    }
}

// ---------------- t[r] = query[r,:].u + s0 ----------------
__global__ void k_t(const float* __restrict__ query) {
    int r = blockIdx.x * 8 + threadIdx.y;
    int lane = threadIdx.x;
    float s = 0.f;
    for (int c = lane; c < CC; c += 32) s += query[(size_t)r * CC + c] * g_u[c];
    #pragma unroll
    for (int o = 16; o; o >>= 1) s += __shfl_xor_sync(0xFFFFFFFFu, s, o);
    if (lane == 0) g_t[r] = s + g_s0[0];
}

// ===== fused logits + softmax(over G) + argmax + counts =====
// Mainloop identical to R3's k_logits (FFMA2-pipe saturated). Epilogue stages the
// 64x128 logits tile into smem (union with sA/sB) and does per-column softmax.
__global__ void __launch_bounds__(128) k_attn(const float* __restrict__ key,
                                              float* __restrict__ soft,
                                              int* __restrict__ idxp,
                                              int* __restrict__ cntp) {
    __shared__ __align__(16) char sbuf[64 * 132 * 4];   // 33792 B
    float (*sA)[72]  = (float(*)[72])sbuf;              // 4608 B (mainloop)
    float (*sB)[136] = (float(*)[136])(sbuf + 4608);    // 8704 B (mainloop)
    float (*S)[132]  = (float(*)[132])sbuf;             // 33792 B (epilogue)
    __shared__ float tsm[GG];

    int b = blockIdx.y;
    int n_base = blockIdx.x * 128;
    int tid = threadIdx.x;
    if (tid < GG) tsm[tid] = g_t[b * GG + tid];

    const float* q2 = g_q2 + (size_t)b * GG * CC;
    const float* kp = key + ((size_t)b * NN + n_base) * CC;

    unsigned long long acc2[8][4];
    #pragma unroll
    for (int i = 0; i < 8; i++)
        #pragma unroll
        for (int j = 0; j < 4; j++) acc2[i][j] = 0ULL;

    for (int k0 = 0; k0 < CC; k0 += 16) {
        {   // A: 64g x 16k  (8 floats / thread)
            int g = tid >> 1, ks = (tid & 1) * 8;
            float4 v0 = *(const float4*)&q2[(size_t)g * CC + k0 + ks];
            float4 v1 = *(const float4*)&q2[(size_t)g * CC + k0 + ks + 4];
            sA[ks + 0][g] = v0.x; sA[ks + 1][g] = v0.y; sA[ks + 2][g] = v0.z; sA[ks + 3][g] = v0.w;
            sA[ks + 4][g] = v1.x; sA[ks + 5][g] = v1.y; sA[ks + 6][g] = v1.z; sA[ks + 7][g] = v1.w;
        }
        #pragma unroll
        for (int p = 0; p < 4; p++) {  // B: 128n x 16k
            int nn = (tid >> 2) + p * 32, kq = (tid & 3) * 4;
            float4 v = *(const float4*)&kp[(size_t)nn * CC + k0 + kq];
            sB[kq + 0][nn] = v.x; sB[kq + 1][nn] = v.y;
            sB[kq + 2][nn] = v.z; sB[kq + 3][nn] = v.w;
        }
        __syncthreads();
        int ty = tid >> 4, tx = tid & 15;
        #pragma unroll
        for (int kk = 0; kk < 16; kk++) {
            float a[8];
            *(float4*)&a[0] = *(const float4*)&sA[kk][ty * 8];
            *(float4*)&a[4] = *(const float4*)&sA[kk][ty * 8 + 4];
            ulonglong2 bb01 = *(const ulonglong2*)&sB[kk][tx * 8 + 0];
            ulonglong2 bb23 = *(const ulonglong2*)&sB[kk][tx * 8 + 4];
            unsigned long long bv[4] = {bb01.x, bb01.y, bb23.x, bb23.y};
            #pragma unroll
            for (int i = 0; i < 8; i++) {
                unsigned long long aa = pack2(a[i], a[i]);
                #pragma unroll
                for (int j = 0; j < 4; j++) fma_f32x2(acc2[i][j], aa, bv[j], acc2[i][j]);
            }
        }
        __syncthreads();
    }

    int ty = tid >> 4, tx = tid & 15;
    // stage logits tile to smem (acc2 dies here -> no register-pressure spike)
    #pragma unroll
    for (int i = 0; i < 8; i++) {
        int g = ty * 8 + i;
        float tb = tsm[g];
        float o[8];
        #pragma unroll
        for (int j = 0; j < 4; j++) {
            float lo, hi;
            unpack2(lo, hi, acc2[i][j]);
            o[2 * j]     = SCALE * (lo + tb);
            o[2 * j + 1] = SCALE * (hi + tb);
        }
        *(float4*)&S[g][tx * 8 + 0] = *(float4*)&o[0];
        *(float4*)&S[g][tx * 8 + 4] = *(float4*)&o[4];
    }
    __syncthreads();
    // per-thread column softmax: thread tid owns n = n_base + tid
    float v[GG];
    float mx = -3.4e38f; int am = 0;
    #pragma unroll
    for (int g = 0; g < GG; g++) {
        float x = S[g][tid];
        v[g] = x;
        if (x > mx) { mx = x; am = g; }   // first max wins (ascending g, strict >)
    }
    float s = 0.f;
    #pragma unroll
    for (int g = 0; g < GG; g++) { v[g] = __expf(v[g] - mx); s += v[g]; }
    float inv = 1.0f / s;
    float* sp = soft + (size_t)b * GG * NN + n_base + tid;
    #pragma unroll
    for (int g = 0; g < GG; g++) sp[(size_t)g * NN] = v[g] * inv;
    idxp[b * NN + n_base + tid] = am;
    atomicAdd(&cntp[b * GG + am], 1);
}

// ---------------- segment sums of key rows by argmax group ----------------
__global__ void __launch_bounds__(128) k_seg(const float* __restrict__ key) {
    __shared__ float S[GG][128];
    __shared__ int sidx[512];
    int ns = blockIdx.x, cb = blockIdx.y, b = blockIdx.z;
    int tid = threadIdx.x;
    int c0 = cb * 128, nb = ns * 512;
    for (int i = tid; i < GG * 128; i += 128) ((float*)S)[i] = 0.f;
    for (int i = tid; i < 512; i += 128) sidx[i] = g_idx[b * NN + nb + i];
    __syncthreads();
    const float* kp = key + ((size_t)(b * NN + nb)) * CC + c0;
    for (int n = 0; n < 512; n += 8) {
        float x[8];
        #pragma unroll
        for (int i = 0; i < 8; i++) x[i] = kp[(size_t)(n + i) * CC + tid];
        #pragma unroll
        for (int i = 0; i < 8; i++) S[sidx[n + i]][tid] += x[i];
    }
    __syncthreads();
    float* dst = g_Sp + (size_t)ns * BB * GG * CC + (size_t)b * GG * CC + c0 + tid;
    for (int g = 0; g < GG; g++) dst[(size_t)g * CC] = S[g][tid];
}

// ---------------- launcher ----------------
extern "C" void kernel_launch(void* const* d_in, const int* in_sizes, int n_in,
                              void* d_out, int out_size) {
    const float* query = (const float*)d_in[0];
    const float* key   = (const float*)d_in[1];
    const float* q_w   = (const float*)d_in[2];
    const float* q_b   = (const float*)d_in[3];
    const float* k_w   = (const float*)d_in[4];
    const float* k_b   = (const float*)d_in[5];
    const float* v_w   = (const float*)d_in[6];
    const float* v_b   = (const float*)d_in[7];
    const float* p_w   = (const float*)d_in[8];
    const float* p_b   = (const float*)d_in[9];
    (void)n_in; (void)in_sizes;

    float* out  = (float*)d_out;
    float* soft = out + ((size_t)out_size - (size_t)BB * GG * NN);

    float *pWq, *pMm, *pbq2, *pq2, *ppvb, *pSp;
    int *pidx, *pcnt;
    cudaGetSymbolAddress((void**)&pWq,  g_Wq);
    cudaGetSymbolAddress((void**)&pMm,  g_Mm);
    cudaGetSymbolAddress((void**)&pbq2, g_bq2);
    cudaGetSymbolAddress((void**)&pq2,  g_q2);
    cudaGetSymbolAddress((void**)&ppvb, g_pvb);
    cudaGetSymbolAddress((void**)&pSp,  g_Sp);
    cudaGetSymbolAddress((void**)&pidx, g_idx);
    cudaGetSymbolAddress((void**)&pcnt, g_cnt);

    // 1. zero counts
    k_zero<<<2, 1024>>>(pcnt);
    // 2. parallel precomputes
    k_prep_cols<<<12, CC>>>(q_w, q_b, k_w, k_b);
    k_prep_pv<<<97, 128>>>(p_w, v_b, q_b, k_b);
    k_prep_red<<<1, CC>>>();
    // 3. Wq = q_w.T @ k_w ; Mm = p_w @ v_w
    k_gemm64<1, 0, 0><<<dim3(6, 6), 256>>>(q_w, k_w, pWq, nullptr, nullptr, nullptr);
    k_gemm64<0, 0, 0><<<dim3(6, 6), 256>>>(p_w, v_w, pMm, nullptr, nullptr, nullptr);
    // 4. t[r]
    k_t<<<BB * GG / 8, dim3(32, 8)>>>(query);
    // 5. q2 = query @ Wq + bq2
    k_gemm64<0, 0, 1><<<dim3(6, 32), 256>>>(query, pWq, pq2, pbq2, nullptr, nullptr);
    // 6. fused logits + softmax + argmax + counts
    k_attn<<<dim3(NN / 128, BB), 128>>>(key, soft, pidx, pcnt);
    // 7. segment sums of key
    k_seg<<<dim3(NSEG, 3, BB), 128>>>(key);
    // 8. out = (S @ Mm.T + cnt*pvb)/(cnt+1) + p_b
    k_gemm64<2, 1, 2><<<dim3(6, 32), 256>>>(pSp, pMm, out, p_b, pcnt, ppvb);
}

// round 8
// speedup vs baseline: 1.2433x; 1.0656x over previous
#include <cuda_runtime.h>
#include <math.h>
#include <stdint.h>

#define BB 32
#define GG 64
#define NN 4096
#define CC 384
#define NSEG 8
#define SCALE 0.051031036307982884f  /* 384^-0.5 */

// ---------------- scratch (device globals; no allocation allowed) ----------------
__device__ float g_Wq[CC*CC];        // q_w.T @ k_w
__device__ float g_Mm[CC*CC];        // p_w @ v_w
__device__ float g_bq2[CC];          // q_b @ k_w
__device__ float g_u[CC];            // q_w.T @ k_b
__device__ float g_pvb[CC];          // p_w @ v_b
__device__ float g_s0[1];            // q_b . k_b
__device__ float g_b2p[12*CC];       // partials for bq2
__device__ float g_up[12*CC];        // partials for u
__device__ float g_q2[BB*GG*CC];     // query @ Wq + bq2
__device__ float g_t[BB*GG];         // per (b,g) bias
__device__ int   g_idx[BB*NN];       // argmax group per (b,n)
__device__ int   g_cnt[BB*GG];       // counts per (b,g)
__device__ float g_Sp[(size_t)NSEG*BB*GG*CC]; // n-segment partial key sums

// ---------------- f32x2 packed helpers (sm_103a) ----------------
__device__ __forceinline__ void fma_f32x2(unsigned long long& d, unsigned long long a,
                                          unsigned long long b, unsigned long long c) {
    asm("fma.rn.f32x2 %0, %1, %2, %3;" : "=l"(d) : "l"(a), "l"(b), "l"(c));
}
__device__ __forceinline__ unsigned long long pack2(float lo, float hi) {
    unsigned long long d;
    asm("mov.b64 %0, {%1, %2};" : "=l"(d) : "f"(lo), "f"(hi));
    return d;
}
__device__ __forceinline__ void unpack2(float& lo, float& hi, unsigned long long v) {
    asm("mov.b64 {%0, %1}, %2;" : "=f"(lo), "=f"(hi) : "l"(v));
}

// ---------------- tf32 helpers (mma.sync path; baseline sm_80+ PTX) ----------------
__device__ __forceinline__ uint32_t tf32hi(float x) {
    uint32_t u;
    asm("cvt.rna.satfinite.tf32.f32 %0, %1;" : "=r"(u) : "f"(x));
    return u;
}
#define MMA_TF32(d, a, b)                                                       \
    asm volatile("mma.sync.aligned.m16n8k8.row.col.f32.tf32.tf32.f32 "          \
        "{%0,%1,%2,%3}, {%4,%5,%6,%7}, {%8,%9}, {%0,%1,%2,%3};"                 \
        : "+f"((d)[0]), "+f"((d)[1]), "+f"((d)[2]), "+f"((d)[3])                \
        : "r"((a)[0]), "r"((a)[1]), "r"((a)[2]), "r"((a)[3]),                   \
          "r"((b)[0]), "r"((b)[1]))

// ---------------- zero counts ----------------
__global__ void k_zero(int* cnt) {
    int t = blockIdx.x * blockDim.x + threadIdx.x;
    if (t < BB*GG) cnt[t] = 0;
}

// ---------------- parallel precompute: column reductions (partials) ----------------
__global__ void __launch_bounds__(CC) k_prep_cols(const float* __restrict__ qw,
                                                  const float* __restrict__ qb,
                                                  const float* __restrict__ kw,
                                                  const float* __restrict__ kb) {
    int j = threadIdx.x;
    int c0 = blockIdx.x * 32;
    float b2 = 0.f, u = 0.f;
    #pragma unroll 8
    for (int c = c0; c < c0 + 32; c++) {
        b2 += qb[c] * kw[(size_t)c * CC + j];
        u  += qw[(size_t)c * CC + j] * kb[c];
    }
    g_b2p[blockIdx.x * CC + j] = b2;
    g_up [blockIdx.x * CC + j] = u;
}

__global__ void k_prep_red() {
    int j = threadIdx.x;
    float b2 = 0.f, u = 0.f;
    #pragma unroll
    for (int p = 0; p < 12; p++) { b2 += g_b2p[p * CC + j]; u += g_up[p * CC + j]; }
    g_bq2[j] = b2; g_u[j] = u;
}

__global__ void __launch_bounds__(128) k_prep_pv(const float* __restrict__ pw,
                                                 const float* __restrict__ vb,
                                                 const float* __restrict__ qb,
                                                 const float* __restrict__ kb) {
    int w = threadIdx.x >> 5, lane = threadIdx.x & 31;
    if (blockIdx.x == 96) {
        if (w == 0) {
            float s = 0.f;
            for (int c = lane; c < CC; c += 32) s += qb[c] * kb[c];
            #pragma unroll
            for (int o = 16; o; o >>= 1) s += __shfl_xor_sync(0xFFFFFFFFu, s, o);
            if (lane == 0) g_s0[0] = s;
        }
        return;
    }
    int j = blockIdx.x * 4 + w;
    float s = 0.f;
    for (int c = lane; c < CC; c += 32) s += pw[(size_t)j * CC + c] * vb[c];
    #pragma unroll
    for (int o = 16; o; o >>= 1) s += __shfl_xor_sync(0xFFFFFFFFu, s, o);
    if (lane == 0) g_pvb[j] = s;
}

// ---------------- generic 64x64-tile fp32 GEMM (f32x2 inner) ----------------
template<int AM, int BM, int EPI>
__global__ void __launch_bounds__(256) k_gemm64(const float* __restrict__ A,
                                                const float* __restrict__ Bm,
                                                float* __restrict__ Cc,
                                                const float* __restrict__ bias,
                                                const int* __restrict__ cnt,
                                                const float* __restrict__ pvb) {
    __shared__ __align__(16) float As[16][68];
    __shared__ __align__(16) float Bs[16][68];
    int j0 = blockIdx.x * 64, i0 = blockIdx.y * 64;
    int tid = threadIdx.x;
    unsigned long long acc2[4][2];
    #pragma unroll
    for (int i = 0; i < 4; i++) { acc2[i][0] = 0ULL; acc2[i][1] = 0ULL; }
    for (int k0 = 0; k0 < CC; k0 += 16) {
        if (AM == 1) {
            int kk = tid >> 4, i4 = (tid & 15) * 4;
            *(float4*)&As[kk][i4] = *(const float4*)&A[(size_t)(k0 + kk) * CC + i0 + i4];
        } else {
            int r = tid >> 2, kq = (tid & 3) * 4;
            float4 v;
            if (AM == 2) {
                const float* p = &A[(size_t)(i0 + r) * CC + k0 + kq];
                const size_t PS = (size_t)BB * GG * CC;
                float4 s = *(const float4*)p;
                #pragma unroll
                for (int q = 1; q < NSEG; q++) {
                    float4 vq = *(const float4*)(p + (size_t)q * PS);
                    s.x += vq.x; s.y += vq.y; s.z += vq.z; s.w += vq.w;
                }
                v = s;
            } else {
                v = *(const float4*)&A[(size_t)(i0 + r) * CC + k0 + kq];
            }
            As[kq + 0][r] = v.x; As[kq + 1][r] = v.y;
            As[kq + 2][r] = v.z; As[kq + 3][r] = v.w;
        }
        if (BM == 0) {
            int kk = tid >> 4, j4 = (tid & 15) * 4;
            *(float4*)&Bs[kk][j4] = *(const float4*)&Bm[(size_t)(k0 + kk) * CC + j0 + j4];
        } else {
            int jr = tid >> 2, kq = (tid & 3) * 4;
            float4 v = *(const float4*)&Bm[(size_t)(j0 + jr) * CC + k0 + kq];
            Bs[kq + 0][jr] = v.x; Bs[kq + 1][jr] = v.y;
            Bs[kq + 2][jr] = v.z; Bs[kq + 3][jr] = v.w;
        }
        __syncthreads();
        int ty = tid >> 4, tx = tid & 15;
        #pragma unroll
        for (int kk = 0; kk < 16; kk++) {
            float4 a4 = *(const float4*)&As[kk][ty * 4];
            ulonglong2 bb = *(const ulonglong2*)&Bs[kk][tx * 4];
            unsigned long long av[4] = {pack2(a4.x, a4.x), pack2(a4.y, a4.y),
                                        pack2(a4.z, a4.z), pack2(a4.w, a4.w)};
            #pragma unroll
            for (int i = 0; i < 4; i++) {
                fma_f32x2(acc2[i][0], av[i], bb.x, acc2[i][0]);
                fma_f32x2(acc2[i][1], av[i], bb.y, acc2[i][1]);
            }
        }
        __syncthreads();
    }
    int ty = tid >> 4, tx = tid & 15;
    #pragma unroll
    for (int i = 0; i < 4; i++) {
        int r = i0 + ty * 4 + i;
        float a0, a1, a2, a3;
        unpack2(a0, a1, acc2[i][0]);
        unpack2(a2, a3, acc2[i][1]);
        float accv[4] = {a0, a1, a2, a3};
        #pragma unroll
        for (int j = 0; j < 4; j++) {
            int c = j0 + tx * 4 + j;
            float v = accv[j];
            if (EPI == 1) v += bias[c];
            if (EPI == 2) {
                float cf = (float)cnt[r];
                v = (v + cf * pvb[c]) / (cf + 1.0f) + bias[c];
            }
            Cc[(size_t)r * CC + c] = v;
        }
    }
}

// ---------------- t[r] = query[r,:].u + s0 ----------------
__global__ void k_t(const float* __restrict__ query) {
    int r = blockIdx.x * 8 + threadIdx.y;
    int lane = threadIdx.x;
    float s = 0.f;
    for (int c = lane; c < CC; c += 32) s += query[(size_t)r * CC + c] * g_u[c];
    #pragma unroll
    for (int o = 16; o; o >>= 1) s += __shfl_xor_sync(0xFFFFFFFFu, s, o);
    if (lane == 0) g_t[r] = s + g_s0[0];
}

// ===== fused logits (tf32x3 mma.sync) + softmax(over G) + argmax + counts =====
// Block: one b, 128-n tile, all 64 g. 128 threads = 4 warps.
// MMA: M=64 (g), warp owns 32-wide n strip -> 4 m-tiles x 4 n-tiles of m16n8k8.
// x = hi + lo (hi = rna-tf32); D += Ah*Bh + Ah*Bl + Al*Bh (lo terms truncated by mma: ~2^-23 total).
__global__ void __launch_bounds__(128) k_attn(const float* __restrict__ key,
                                              float* __restrict__ soft,
                                              int* __restrict__ idxp,
                                              int* __restrict__ cntp) {
    __shared__ __align__(16) char sbuf[33792];
    float (*sAh)[72]  = (float(*)[72])sbuf;                   // 4608 B
    float (*sAl)[72]  = (float(*)[72])(sbuf + 4608);          // 4608 B
    float (*sBh)[136] = (float(*)[136])(sbuf + 9216);         // 8704 B
    float (*sBl)[136] = (float(*)[136])(sbuf + 17920);        // 8704 B -> 26624
    float (*S)[132]   = (float(*)[132])sbuf;                  // 33792 B (epilogue)
    __shared__ float tsm[GG];

    int b = blockIdx.y;
    int n_base = blockIdx.x * 128;
    int tid = threadIdx.x, lane = tid & 31, warp = tid >> 5;
    if (tid < GG) tsm[tid] = g_t[b * GG + tid];

    const float* q2 = g_q2 + (size_t)b * GG * CC;
    const float* kp = key + ((size_t)b * NN + n_base) * CC;

    float acc[4][4][4];
    #pragma unroll
    for (int mt = 0; mt < 4; mt++)
        #pragma unroll
        for (int nt = 0; nt < 4; nt++)
            #pragma unroll
            for (int r = 0; r < 4; r++) acc[mt][nt][r] = 0.f;

    int kr = lane & 3, gr = lane >> 2;   // fragment row/col helpers
    int wb = warp * 32;                  // warp's n strip

    for (int k0 = 0; k0 < CC; k0 += 16) {
        {   // A (q2): 64g x 16k, split hi/lo
            int g = tid >> 1, ks = (tid & 1) * 8;
            float4 v0 = *(const float4*)&q2[(size_t)g * CC + k0 + ks];
            float4 v1 = *(const float4*)&q2[(size_t)g * CC + k0 + ks + 4];
            float f[8] = {v0.x, v0.y, v0.z, v0.w, v1.x, v1.y, v1.z, v1.w};
            #pragma unroll
            for (int i = 0; i < 8; i++) {
                float h = __uint_as_float(tf32hi(f[i]));
                sAh[ks + i][g] = h;
                sAl[ks + i][g] = f[i] - h;
            }
        }
        #pragma unroll
        for (int p = 0; p < 4; p++) {  // B (key): 128n x 16k, split hi/lo
            int nn = (tid >> 2) + p * 32, kq = (tid & 3) * 4;
            float4 v = *(const float4*)&kp[(size_t)nn * CC + k0 + kq];
            float f[4] = {v.x, v.y, v.z, v.w};
            #pragma unroll
            for (int i = 0; i < 4; i++) {
                float h = __uint_as_float(tf32hi(f[i]));
                sBh[kq + i][nn] = h;
                sBl[kq + i][nn] = f[i] - h;
            }
        }
        __syncthreads();
        #pragma unroll
        for (int s = 0; s < 2; s++) {   // two k8 steps per chunk
            int k1 = s * 8 + kr, k2 = k1 + 4;
            uint32_t bh[4][2], bl[4][2];
            #pragma unroll
            for (int nt = 0; nt < 4; nt++) {
                int nc = wb + nt * 8 + gr;
                bh[nt][0] = __float_as_uint(sBh[k1][nc]);
                bh[nt][1] = __float_as_uint(sBh[k2][nc]);
                bl[nt][0] = __float_as_uint(sBl[k1][nc]);
                bl[nt][1] = __float_as_uint(sBl[k2][nc]);
            }
            #pragma unroll
            for (int mt = 0; mt < 4; mt++) {
                int g0 = mt * 16 + gr;
                uint32_t ah[4], al[4];
                ah[0] = __float_as_uint(sAh[k1][g0]);
                ah[1] = __float_as_uint(sAh[k1][g0 + 8]);
                ah[2] = __float_as_uint(sAh[k2][g0]);
                ah[3] = __float_as_uint(sAh[k2][g0 + 8]);
                al[0] = __float_as_uint(sAl[k1][g0]);
                al[1] = __float_as_uint(sAl[k1][g0 + 8]);
                al[2] = __float_as_uint(sAl[k2][g0]);
                al[3] = __float_as_uint(sAl[k2][g0 + 8]);
                #pragma unroll
                for (int nt = 0; nt < 4; nt++) {
                    MMA_TF32(acc[mt][nt], ah, bh[nt]);
                    MMA_TF32(acc[mt][nt], ah, bl[nt]);
                    MMA_TF32(acc[mt][nt], al, bh[nt]);
                }
            }
        }
        __syncthreads();
    }

    // stage D to S with scale + bias  (c0:(gr,2kr) c1:(gr,2kr+1) c2:(gr+8,2kr) c3:(gr+8,2kr+1))
    #pragma unroll
    for (int mt = 0; mt < 4; mt++) {
        int g0 = mt * 16 + gr, g1 = g0 + 8;
        float t0 = tsm[g0], t1 = tsm[g1];
        #pragma unroll
        for (int nt = 0; nt < 4; nt++) {
            int c = wb + nt * 8 + 2 * kr;
            *(float2*)&S[g0][c] = make_float2(SCALE * (acc[mt][nt][0] + t0),
                                              SCALE * (acc[mt][nt][1] + t0));
            *(float2*)&S[g1][c] = make_float2(SCALE * (acc[mt][nt][2] + t1),
                                              SCALE * (acc[mt][nt][3] + t1));
        }
    }
    __syncthreads();
    // per-thread column softmax: thread tid owns n = n_base + tid
    float v[GG];
    float mx = -3.4e38f; int am = 0;
    #pragma unroll
    for (int g = 0; g < GG; g++) {
        float x = S[g][tid];
        v[g] = x;
        if (x > mx) { mx = x; am = g; }   // first max wins (ascending g, strict >)
    }
    float s = 0.f;
    #pragma unroll
    for (int g = 0; g < GG; g++) { v[g] = __expf(v[g] - mx); s += v[g]; }
    float inv = 1.0f / s;
    float* sp = soft + (size_t)b * GG * NN + n_base + tid;
    #pragma unroll
    for (int g = 0; g < GG; g++) sp[(size_t)g * NN] = v[g] * inv;
    idxp[b * NN + n_base + tid] = am;
    atomicAdd(&cntp[b * GG + am], 1);
}

// ---------------- segment sums of key rows by argmax group ----------------
__global__ void __launch_bounds__(128) k_seg(const float* __restrict__ key) {
    __shared__ float S[GG][128];
    __shared__ int sidx[512];
    int ns = blockIdx.x, cb = blockIdx.y, b = blockIdx.z;
    int tid = threadIdx.x;
    int c0 = cb * 128, nb = ns * 512;
    for (int i = tid; i < GG * 128; i += 128) ((float*)S)[i] = 0.f;
    for (int i = tid; i < 512; i += 128) sidx[i] = g_idx[b * NN + nb + i];
    __syncthreads();
    const float* kp = key + ((size_t)(b * NN + nb)) * CC + c0;
    for (int n = 0; n < 512; n += 8) {
        float x[8];
        #pragma unroll
        for (int i = 0; i < 8; i++) x[i] = kp[(size_t)(n + i) * CC + tid];
        #pragma unroll
        for (int i = 0; i < 8; i++) S[sidx[n + i]][tid] += x[i];
    }
    __syncthreads();
    float* dst = g_Sp + (size_t)ns * BB * GG * CC + (size_t)b * GG * CC + c0 + tid;
    for (int g = 0; g < GG; g++) dst[(size_t)g * CC] = S[g][tid];
}

// ---------------- launcher ----------------
extern "C" void kernel_launch(void* const* d_in, const int* in_sizes, int n_in,
                              void* d_out, int out_size) {
    const float* query = (const float*)d_in[0];
    const float* key   = (const float*)d_in[1];
    const float* q_w   = (const float*)d_in[2];
    const float* q_b   = (const float*)d_in[3];
    const float* k_w   = (const float*)d_in[4];
    const float* k_b   = (const float*)d_in[5];
    const float* v_w   = (const float*)d_in[6];
    const float* v_b   = (const float*)d_in[7];
    const float* p_w   = (const float*)d_in[8];
    const float* p_b   = (const float*)d_in[9];
    (void)n_in; (void)in_sizes;

    float* out  = (float*)d_out;
    float* soft = out + ((size_t)out_size - (size_t)BB * GG * NN);

    float *pWq, *pMm, *pbq2, *pq2, *ppvb, *pSp;
    int *pidx, *pcnt;
    cudaGetSymbolAddress((void**)&pWq,  g_Wq);
    cudaGetSymbolAddress((void**)&pMm,  g_Mm);
    cudaGetSymbolAddress((void**)&pbq2, g_bq2);
    cudaGetSymbolAddress((void**)&pq2,  g_q2);
    cudaGetSymbolAddress((void**)&ppvb, g_pvb);
    cudaGetSymbolAddress((void**)&pSp,  g_Sp);
    cudaGetSymbolAddress((void**)&pidx, g_idx);
    cudaGetSymbolAddress((void**)&pcnt, g_cnt);

    // 1. zero counts
    k_zero<<<2, 1024>>>(pcnt);
    // 2. parallel precomputes
    k_prep_cols<<<12, CC>>>(q_w, q_b, k_w, k_b);
    k_prep_pv<<<97, 128>>>(p_w, v_b, q_b, k_b);
    k_prep_red<<<1, CC>>>();
    // 3. Wq = q_w.T @ k_w ; Mm = p_w @ v_w
    k_gemm64<1, 0, 0><<<dim3(6, 6), 256>>>(q_w, k_w, pWq, nullptr, nullptr, nullptr);
    k_gemm64<0, 0, 0><<<dim3(6, 6), 256>>>(p_w, v_w, pMm, nullptr, nullptr, nullptr);
    // 4. t[r]
    k_t<<<BB * GG / 8, dim3(32, 8)>>>(query);
    // 5. q2 = query @ Wq + bq2
    k_gemm64<0, 0, 1><<<dim3(6, 32), 256>>>(query, pWq, pq2, pbq2, nullptr, nullptr);
    // 6. fused logits(tf32x3 mma) + softmax + argmax + counts
    k_attn<<<dim3(NN / 128, BB), 128>>>(key, soft, pidx, pcnt);
    // 7. segment sums of key
    k_seg<<<dim3(NSEG, 3, BB), 128>>>(key);
    // 8. out = (S @ Mm.T + cnt*pvb)/(cnt+1) + p_b
    k_gemm64<2, 1, 2><<<dim3(6, 32), 256>>>(pSp, pMm, out, p_b, pcnt, ppvb);
}